// round 1
// baseline (speedup 1.0000x reference)
#include <cuda_runtime.h>
#include <cuda_bf16.h>

// Problem constants (fixed shapes from setup_inputs)
#define BB 32
#define DD 32
#define HH 32
#define WW 32
#define PS 4
#define NPD 8            // D/PS
#define NPH 8            // H/PS
#define NPW 8            // W/PS
#define PATCHES_PER_BLOCK 8          // all 8 w-patches of one (b,pd,ph) row-slab
#define NUM_BLOCKS (BB * NPD * NPH)  // 2048
#define TOTAL_PATCHES (BB * NPD * NPH * NPW)  // 16384
#define TOKENS 64
#define AIR0 102
#define AIR1 576
#define AIR2 3352

// Scratch: per-patch entropy (no cudaMalloc allowed)
__device__ float g_patch_entropy[TOTAL_PATCHES];

// Kernel A: one block handles 8 patches (a full 4x4x32 slab).
// 512 threads: thread = 64 per patch.
__global__ __launch_bounds__(512, 4)
void patch_entropy_kernel(const int* __restrict__ s) {
    // Padded per-patch token store: stride 68 => conflict-free STS across the 8 patches
    __shared__ int sm[PATCHES_PER_BLOCK * 68];
    __shared__ int red_tot[16];    // one per warp (16 warps)
    __shared__ float red_ent[16];

    const int blk = blockIdx.x;
    const int b  = blk >> 6;          // /64
    const int rem = blk & 63;
    const int pd = rem >> 3;
    const int ph = rem & 7;
    // base element offset of this slab
    const int base = b * (DD * HH * WW) + pd * (PS * HH * WW) + ph * (PS * WW);

    const int tid = threadIdx.x;

    // ---- coalesced load of the 4x4x32 slab (512 int32) ----
    {
        const int d = tid >> 7;          // 0..3
        const int h = (tid >> 5) & 3;    // 0..3
        const int w = tid & 31;          // 0..31
        const int v = s[base + d * (HH * WW) + h * WW + w];
        const int p = w >> 2;                       // which w-patch
        const int t = d * 16 + h * 4 + (w & 3);     // token index within patch
        sm[p * 68 + t] = v;
    }
    __syncthreads();

    // ---- per-token duplicate/count pass (O(64) per thread, LDS broadcast) ----
    const int pp = tid >> 6;   // patch within block, 0..7
    const int tt = tid & 63;   // token index, 0..63
    const int* patch_base = &sm[pp * 68];

    const int v = patch_base[tt];
    const bool is_air = (v == AIR0) | (v == AIR1) | (v == AIR2);

    int c = 0;      // occurrence count of v within patch
    int dup = 0;    // nonzero if an earlier index holds the same value
    #pragma unroll 16
    for (int k = 0; k < TOKENS; ++k) {
        const int u = patch_base[k];   // broadcast read within each warp
        const int eq = (u == v);
        c += eq;
        dup += eq & (k < tt);
    }

    // ---- reduce tot = # non-air tokens over the 64-thread group (2 warps) ----
    const int wid = tid >> 5;    // 0..15, warps 2p and 2p+1 belong to patch p
    const int lane = tid & 31;
    int tot = is_air ? 0 : 1;
    #pragma unroll
    for (int off = 16; off > 0; off >>= 1)
        tot += __shfl_down_sync(0xFFFFFFFFu, tot, off);
    if (lane == 0) red_tot[wid] = tot;
    __syncthreads();
    const int tot_patch = red_tot[2 * pp] + red_tot[2 * pp + 1];

    // ---- entropy term: only first occurrences of non-air tokens contribute ----
    float term = 0.0f;
    if (!is_air && dup == 0) {
        const float inv_tot = 1.0f / (float)max(tot_patch, 1);
        const float p = (float)c * inv_tot;
        term = -p * __logf(p + 1e-10f);
    }
    #pragma unroll
    for (int off = 16; off > 0; off >>= 1)
        term += __shfl_down_sync(0xFFFFFFFFu, term, off);
    if (lane == 0) red_ent[wid] = term;
    __syncthreads();

    if (tt == 0) {
        const float ent = red_ent[2 * pp] + red_ent[2 * pp + 1];
        g_patch_entropy[blk * PATCHES_PER_BLOCK + pp] = ent;
    }
}

// Kernel B: deterministic single-block reduction of 16384 patch entropies.
__global__ __launch_bounds__(512, 1)
void final_reduce_kernel(float* __restrict__ out) {
    __shared__ double red[16];
    const int tid = threadIdx.x;

    double acc = 0.0;
    #pragma unroll 8
    for (int i = tid; i < TOTAL_PATCHES; i += 512)
        acc += (double)g_patch_entropy[i];

    #pragma unroll
    for (int off = 16; off > 0; off >>= 1)
        acc += __shfl_down_sync(0xFFFFFFFFu, acc, off);
    if ((tid & 31) == 0) red[tid >> 5] = acc;
    __syncthreads();

    if (tid == 0) {
        double total = 0.0;
        #pragma unroll
        for (int w = 0; w < 16; ++w) total += red[w];
        out[0] = (float)(total / ((double)TOTAL_PATCHES + 1e-06));
    }
}

extern "C" void kernel_launch(void* const* d_in, const int* in_sizes, int n_in,
                              void* d_out, int out_size) {
    const int* structure = (const int*)d_in[0];
    float* out = (float*)d_out;
    patch_entropy_kernel<<<NUM_BLOCKS, 512>>>(structure);
    final_reduce_kernel<<<1, 512>>>(out);
}

// round 2
// speedup vs baseline: 1.9422x; 1.9422x over previous
#include <cuda_runtime.h>
#include <cuda_bf16.h>

// Problem constants (fixed shapes from setup_inputs)
#define BB 32
#define DD 32
#define HH 32
#define WW 32
#define PS 4
#define NPD 8
#define NPH 8
#define NPW 8
#define PATCHES_PER_BLOCK 8
#define NUM_BLOCKS (BB * NPD * NPH)           // 2048
#define TOTAL_PATCHES (BB * NPD * NPH * NPW)  // 16384
#define TOKENS 64
#define AIR0 102
#define AIR1 576
#define AIR2 3352
#define FP_SCALE 4294967296.0   // 2^32 fixed-point scale for deterministic atomics

// Zero-initialized at module load; last block resets them each run (graph-replay safe).
__device__ unsigned long long g_acc = 0ULL;
__device__ unsigned int g_ticket = 0u;

// One block = one (b,pd,ph) slab = 8 patches. 512 threads, 64 per patch.
__global__ __launch_bounds__(512, 4)
void patch_entropy_fused_kernel(const int* __restrict__ s, float* __restrict__ out) {
    // stride 68 ints (272 B, 16B-aligned) => conflict-free STS, int4-aligned patches
    __shared__ int sm[PATCHES_PER_BLOCK * 68];
    __shared__ int warp_nonair[16];
    __shared__ float red_ent[16];

    const int blk = blockIdx.x;
    const int b   = blk >> 6;
    const int rem = blk & 63;
    const int pd  = rem >> 3;
    const int ph  = rem & 7;
    const int base = b * (DD * HH * WW) + pd * (PS * HH * WW) + ph * (PS * WW);

    const int tid  = threadIdx.x;
    const int wid  = tid >> 5;
    const int lane = tid & 31;

    // ---- coalesced load of the 4x4x32 slab (512 int32) ----
    {
        const int d = tid >> 7;
        const int h = (tid >> 5) & 3;
        const int w = tid & 31;
        const int v = s[base + d * (HH * WW) + h * WW + w];
        const int p = w >> 2;
        const int t = d * 16 + h * 4 + (w & 3);
        sm[p * 68 + t] = v;   // bank = 4*p + (w&3): conflict-free
    }
    __syncthreads();

    const int pp = tid >> 6;   // patch 0..7 (uniform within each warp)
    const int tt = tid & 63;   // token 0..63

    const int v = sm[pp * 68 + tt];
    const bool is_air = (v == AIR0) | (v == AIR1) | (v == AIR2);

    // non-air count per warp via ballot; combine the patch's two warps via smem
    const unsigned nonair_mask = __ballot_sync(0xFFFFFFFFu, !is_air);
    if (lane == 0) warp_nonair[wid] = __popc(nonair_mask);
    __syncthreads();
    const int tot = warp_nonair[2 * pp] + warp_nonair[2 * pp + 1];

    // ---- occurrence count: 16x LDS.128 broadcast + 64 compares ----
    const int4* pb = reinterpret_cast<const int4*>(&sm[pp * 68]);
    int c = 0;
    #pragma unroll
    for (int k = 0; k < 16; ++k) {
        const int4 u = pb[k];
        c += (u.x == v) + (u.y == v) + (u.z == v) + (u.w == v);
    }

    // Each of the c occurrences contributes (-p*log(p+eps))/c = -(1/tot)*log(p+eps).
    // Summed over occurrences this reproduces the unique-value entropy exactly.
    float term = 0.0f;
    if (!is_air) {
        const float inv_tot = 1.0f / (float)tot;      // tot >= 1 when any non-air exists
        const float p = (float)c * inv_tot;
        term = -inv_tot * __logf(p + 1e-10f);
    }

    // ---- warp reduce -> smem -> warp0 block reduce -> one atomic per block ----
    #pragma unroll
    for (int off = 16; off > 0; off >>= 1)
        term += __shfl_xor_sync(0xFFFFFFFFu, term, off);
    if (lane == 0) red_ent[wid] = term;
    __syncthreads();

    if (wid == 0) {
        float x = (lane < 16) ? red_ent[lane] : 0.0f;
        #pragma unroll
        for (int off = 8; off > 0; off >>= 1)
            x += __shfl_xor_sync(0xFFFFFFFFu, x, off);
        if (lane == 0) {
            // fixed-point accumulate: integer atomics are order-invariant => deterministic
            const unsigned long long q =
                (unsigned long long)(long long)((double)x * FP_SCALE);
            atomicAdd(&g_acc, q);
            __threadfence();
            const unsigned int old = atomicAdd(&g_ticket, 1u);
            if (old == NUM_BLOCKS - 1) {
                // all blocks' accumulator atomics are visible (fence-before-ticket)
                const unsigned long long a = atomicAdd(&g_acc, 0ULL);
                const double total = (double)a / FP_SCALE;
                out[0] = (float)(total / ((double)TOTAL_PATCHES + 1e-06));
                // self-clean for the next graph replay
                g_acc = 0ULL;
                g_ticket = 0u;
            }
        }
    }
}

extern "C" void kernel_launch(void* const* d_in, const int* in_sizes, int n_in,
                              void* d_out, int out_size) {
    const int* structure = (const int*)d_in[0];
    float* out = (float*)d_out;
    patch_entropy_fused_kernel<<<NUM_BLOCKS, 512>>>(structure, out);
}